// round 13
// baseline (speedup 1.0000x reference)
#include <cuda_runtime.h>
#include <cuda_bf16.h>
#include <math.h>
#include <stdint.h>

#define B_    512
#define EMB_  512
#define CLS_  70722
#define BK    32
#define NITER 16          // 512 / 32 (HMMA path)
#define NT    256
#define NSM   148

// A/B bf16 smem rows padded to 40 bf16 (80 B): conflict-free ldmatrix
#define APITCH 80

// dynamic smem offsets (bytes) — HMMA path; SIMT path reuses [0, 32KB)
#define OFF_A     0        // [var(hi/lo)][buf(0/1)] : 4 x (128*80) = 40960
#define OFF_B     40960    // [var(hi/lo)]           : 2 x (128*80) = 20480
#define OFF_STAGE 61440    // fp32 B stage [buf(0/1)][32][128] : 2 x 16384
#define OFF_SUMSQ 94208    // 128 f32
#define OFF_INV   94720    // 128 f32
#define OFF_LAB   95232    // 128 i32
#define OFF_MS    95744    // 128 f32
#define SMEM_TOTAL 96256

__device__ float g_ms[B_];
__device__ __align__(16) __nv_bfloat16 g_Ahi[B_ * EMB_];
__device__ __align__(16) __nv_bfloat16 g_Alo[B_ * EMB_];

// ---------------- PTX helpers (sm_80-era, family-target legal) --------------
__device__ __forceinline__ uint32_t smem_u32(const void* p) {
    uint32_t a;
    asm("{ .reg .u64 t; cvta.to.shared.u64 t, %1; cvt.u32.u64 %0, t; }"
        : "=r"(a) : "l"(p));
    return a;
}
__device__ __forceinline__ void cp16(uint32_t dst, const void* src) {
    asm volatile("cp.async.cg.shared.global [%0], [%1], 16;"
                 :: "r"(dst), "l"(src) : "memory");
}
__device__ __forceinline__ void cp8(uint32_t dst, const void* src) {
    asm volatile("cp.async.ca.shared.global [%0], [%1], 8;"
                 :: "r"(dst), "l"(src) : "memory");
}
__device__ __forceinline__ void ldm4(uint32_t* r, uint32_t addr) {
    asm volatile("ldmatrix.sync.aligned.m8n8.x4.shared.b16 {%0,%1,%2,%3}, [%4];"
                 : "=r"(r[0]), "=r"(r[1]), "=r"(r[2]), "=r"(r[3]) : "r"(addr));
}
__device__ __forceinline__ void mma16816(float* c, const uint32_t* a,
                                         uint32_t b0, uint32_t b1) {
    asm volatile(
        "mma.sync.aligned.m16n8k16.row.col.f32.bf16.bf16.f32 "
        "{%0,%1,%2,%3}, {%4,%5,%6,%7}, {%8,%9}, {%0,%1,%2,%3};"
        : "+f"(c[0]), "+f"(c[1]), "+f"(c[2]), "+f"(c[3])
        : "r"(a[0]), "r"(a[1]), "r"(a[2]), "r"(a[3]), "r"(b0), "r"(b1));
}

// ---------------------------------------------------------------------------
// Kernel 1: per-row margin scaler ms[i] (single block, 512 threads)
// ---------------------------------------------------------------------------
__global__ void margin_kernel(const float* __restrict__ norms,
                              const float* __restrict__ csn) {
    __shared__ float red[B_];
    int t = threadIdx.x;
    float x = fminf(fmaxf(norms[t], 0.001f), 100.0f);
    x = x / (csn[t] + 0.001f);
    x = fminf(fmaxf(x, 0.001f), 100.0f);

    red[t] = x;
    __syncthreads();
    for (int s = B_ / 2; s > 0; s >>= 1) {
        if (t < s) red[t] += red[t + s];
        __syncthreads();
    }
    float mean = red[0] * (1.0f / B_);
    __syncthreads();
    float d = x - mean;
    red[t] = d * d;
    __syncthreads();
    for (int s = B_ / 2; s > 0; s >>= 1) {
        if (t < s) red[t] += red[t + s];
        __syncthreads();
    }
    float stdv = sqrtf(red[0] / (float)(B_ - 1));
    float msc = (x - mean) / (stdv + 0.001f) * 0.333f;
    g_ms[t] = fminf(fmaxf(msc, -1.0f), 1.0f);
}

// ---------------------------------------------------------------------------
// Kernel 2: split embeddings fp32 -> bf16 hi/lo (row-major [512][512])
// ---------------------------------------------------------------------------
__global__ void prepA_kernel(const float* __restrict__ E) {
    int i = blockIdx.x * blockDim.x + threadIdx.x;
    if (i >= B_ * EMB_) return;
    float x = E[i];
    __nv_bfloat16 h = __float2bfloat16(x);
    float r = x - __bfloat162float(h);
    g_Ahi[i] = h;
    g_Alo[i] = __float2bfloat16(r);
}

// ---------------------------------------------------------------------------
// Kernel 3: heterogeneous grid. 2212 CTAs; 148-bid groups 1,5,9,13 run the
// SIMT fp32 path (FMA pipe), the rest run HMMA 3xBF16 (tensor pipe).
// Wave-1 pairing: bids b and b+148 co-reside -> one CTA of each flavor/SM.
// ---------------------------------------------------------------------------
__global__ __launch_bounds__(NT, 2) void gemm_hybrid(
    const float* __restrict__ E,
    const float* __restrict__ Kmat,
    const int* __restrict__ label,
    float* __restrict__ out)
{
    extern __shared__ char smem[];
    const uint32_t sb = smem_u32(smem);
    const int tid  = threadIdx.x;
    const int warp = tid >> 5;
    const int lane = tid & 31;

    // ---- bid -> (type, tile) mapping ----
    const int bid = blockIdx.x;
    const int g   = bid / NSM;
    const int r   = bid % NSM;
    const bool is_simt = (g == 1) | (g == 5) | (g == 9) | (g == 13);
    const int srank = (g > 1) + (g > 5) + (g > 9) + (g > 13);
    int gtile;
    if (is_simt) gtile = srank * NSM + r;                 // 0..591
    else         gtile = 592 + (g - srank) * NSM + r;     // 592..2211
    const int row0 = (gtile & 3) * 128;
    const int col0 = (gtile >> 2) * 128;

    float* s_sumsq = (float*)(smem + OFF_SUMSQ);
    float* s_inv   = (float*)(smem + OFF_INV);
    int*   s_lab   = (int*)(smem + OFF_LAB);
    float* s_ms    = (float*)(smem + OFF_MS);

    const float PI_F = 3.14159265358979323846f;

    if (tid < 128) {
        s_sumsq[tid] = 0.0f;
        s_lab[tid]   = label[row0 + tid];
        s_ms[tid]    = g_ms[row0 + tid];
    }

    if (is_simt) {
        // ================= SIMT fp32 path (tiles are always full) ==========
        // 128x128 tile, BK=16, 32 k-tiles, 8x8 microtile per thread.
        float* As  = (float*)(smem);          // [16][128] (A^T: As[k][m])
        float* BsF = (float*)(smem + 8192);   // [16][128]

        const int tx = tid & 15;
        const int ty = tid >> 4;

        float4 aReg[2];
        float2 bReg[4];
        float acc[8][8];
#pragma unroll
        for (int m = 0; m < 8; m++)
#pragma unroll
            for (int n = 0; n < 8; n++) acc[m][n] = 0.0f;
        float ssq = 0.0f;

        auto loadA = [&](int kt, float4* rr) {
#pragma unroll
            for (int u = 0; u < 2; u++) {
                int idx = tid + u * 256;
                rr[u] = *reinterpret_cast<const float4*>(
                    &E[(size_t)(row0 + (idx >> 2)) * EMB_ + kt + ((idx & 3) << 2)]);
            }
        };
        auto loadB = [&](int kt, float2* rr) {
#pragma unroll
            for (int u = 0; u < 4; u++) {
                int idx = tid + u * 256;
                rr[u] = *reinterpret_cast<const float2*>(
                    &Kmat[(size_t)(kt + (idx >> 6)) * CLS_ + col0 + ((idx & 63) << 1)]);
            }
        };
        auto storeA = [&](float4* rr) {
#pragma unroll
            for (int u = 0; u < 2; u++) {
                int idx = tid + u * 256;
                int ar  = idx >> 2;
                int ac  = (idx & 3) << 2;
                As[(ac + 0) * 128 + ar] = rr[u].x;
                As[(ac + 1) * 128 + ar] = rr[u].y;
                As[(ac + 2) * 128 + ar] = rr[u].z;
                As[(ac + 3) * 128 + ar] = rr[u].w;
            }
        };
        auto storeB = [&](float2* rr) {
#pragma unroll
            for (int u = 0; u < 4; u++) {
                int idx = tid + u * 256;
                *reinterpret_cast<float2*>(
                    &BsF[(idx >> 6) * 128 + ((idx & 63) << 1)]) = rr[u];
            }
        };

        loadA(0, aReg); loadB(0, bReg);
        storeA(aReg);   storeB(bReg);
        __syncthreads();

        const int KT = EMB_ / 16;   // 32
        for (int t = 0; t < KT; t++) {
            if (t + 1 < KT) { loadA((t + 1) * 16, aReg); loadB((t + 1) * 16, bReg); }
            // fused colnorm: this tile's Bs sum-of-squares (before overwrite)
#pragma unroll
            for (int k = 0; k < 8; k++) {
                float v = BsF[((tid >> 7) * 8 + k) * 128 + (tid & 127)];
                ssq = fmaf(v, v, ssq);
            }
#pragma unroll
            for (int k = 0; k < 16; k++) {
                float4 a0 = *reinterpret_cast<const float4*>(&As[k * 128 + ty * 8]);
                float4 a1 = *reinterpret_cast<const float4*>(&As[k * 128 + ty * 8 + 4]);
                float4 b0 = *reinterpret_cast<const float4*>(&BsF[k * 128 + tx * 4]);
                float4 b1 = *reinterpret_cast<const float4*>(&BsF[k * 128 + tx * 4 + 64]);
                float a[8] = {a0.x, a0.y, a0.z, a0.w, a1.x, a1.y, a1.z, a1.w};
                float b[8] = {b0.x, b0.y, b0.z, b0.w, b1.x, b1.y, b1.z, b1.w};
#pragma unroll
                for (int m = 0; m < 8; m++)
#pragma unroll
                    for (int n = 0; n < 8; n++)
                        acc[m][n] = fmaf(a[m], b[n], acc[m][n]);
            }
            __syncthreads();
            if (t + 1 < KT) { storeA(aReg); storeB(bReg); __syncthreads(); }
        }

        atomicAdd(&s_sumsq[tid & 127], ssq * 0.5f);  // two threads own each col
        __syncthreads();
        if (tid < 128) s_inv[tid] = rsqrtf(s_sumsq[tid] * 2.0f);
        __syncthreads();

#pragma unroll
        for (int m = 0; m < 8; m++) {
            int   rl  = ty * 8 + m;
            int   lab = s_lab[rl];
            float ms  = s_ms[rl];
            float* orow = &out[(size_t)(row0 + rl) * CLS_];
#pragma unroll
            for (int n = 0; n < 8; n++) {
                int cl = (n < 4) ? (tx * 4 + n) : (64 + tx * 4 + (n - 4));
                int j  = col0 + cl;
                float c = acc[m][n] * s_inv[cl];
                c = fminf(fmaxf(c, -0.999f), 0.999f);
                float o;
                if (j == lab) {
                    float th = acosf(c) - 0.4f * ms;
                    th = fminf(fmaxf(th, 0.001f), PI_F - 0.001f);
                    o = (cosf(th) - (0.4f + 0.4f * ms)) * 64.0f;
                } else {
                    o = c * 64.0f;
                }
                orow[j] = o;
            }
        }
        return;
    }

    // ===================== HMMA 3xBF16 path ================================
    const int wm = warp >> 2;
    const int wn = warp & 3;
    float* stage = (float*)(smem + OFF_STAGE);

    const int rA = ((lane >> 3) & 1) * 8 + (lane & 7);
    const int cA = ((lane >> 4) & 1) * 8;
    const int rB = (lane & 7) + ((lane >> 4) & 1) * 8;
    const int cB = ((lane >> 3) & 1) * 8;

    float acc[4][4][4];
#pragma unroll
    for (int mf = 0; mf < 4; mf++)
#pragma unroll
        for (int nf = 0; nf < 4; nf++)
#pragma unroll
            for (int q = 0; q < 4; q++) acc[mf][nf][q] = 0.0f;

    auto issueAB = [&](int t, int buf) {
        int kt = t * BK;
#pragma unroll
        for (int u = 0; u < 4; u++) {
            int idx = u * 256 + tid;
            int var = idx >> 9;
            int rs  = idx & 511;
            int m   = rs >> 2;
            int seg = rs & 3;
            const __nv_bfloat16* gp =
                (var ? g_Alo : g_Ahi) + (size_t)(row0 + m) * EMB_ + kt + seg * 8;
            cp16(sb + OFF_A + (uint32_t)(var * 2 + buf) * 10240 +
                     (uint32_t)m * APITCH + seg * 16, gp);
        }
#pragma unroll
        for (int u = 0; u < 8; u++) {
            int idx = u * 256 + tid;
            int k   = idx >> 6;
            int c2  = idx & 63;
            int col = col0 + 2 * c2;
            uint32_t dst = sb + OFF_STAGE + (uint32_t)buf * 16384 +
                           (uint32_t)(k * 128 + 2 * c2) * 4;
            if (col < CLS_) {
                cp8(dst, Kmat + (size_t)(kt + k) * CLS_ + col);
            } else {
                *(float2*)(smem + (dst - sb)) = make_float2(0.0f, 0.0f);
            }
        }
        asm volatile("cp.async.commit_group;" ::: "memory");
    };
    auto convertB = [&](int buf) {
        const int nloc = tid & 127;
        const float* st = stage + buf * 4096 + (tid >> 7) * 16 * 128 + nloc;
        float ss = 0.0f;
        uint32_t hi[8], lo[8];
#pragma unroll
        for (int i = 0; i < 8; i++) {
            float x0 = st[(2 * i) * 128];
            float x1 = st[(2 * i + 1) * 128];
            ss += x0 * x0 + x1 * x1;
            __nv_bfloat16 h0 = __float2bfloat16(x0);
            __nv_bfloat16 h1 = __float2bfloat16(x1);
            float r0 = x0 - __bfloat162float(h0);
            float r1 = x1 - __bfloat162float(h1);
            __nv_bfloat16 l0 = __float2bfloat16(r0);
            __nv_bfloat16 l1 = __float2bfloat16(r1);
            hi[i] = (uint32_t)__bfloat16_as_ushort(h0) |
                    ((uint32_t)__bfloat16_as_ushort(h1) << 16);
            lo[i] = (uint32_t)__bfloat16_as_ushort(l0) |
                    ((uint32_t)__bfloat16_as_ushort(l1) << 16);
        }
        char* bh = smem + OFF_B + nloc * APITCH + (tid >> 7) * 32;
        char* bl = bh + 10240;
        *(uint4*)(bh)      = make_uint4(hi[0], hi[1], hi[2], hi[3]);
        *(uint4*)(bh + 16) = make_uint4(hi[4], hi[5], hi[6], hi[7]);
        *(uint4*)(bl)      = make_uint4(lo[0], lo[1], lo[2], lo[3]);
        *(uint4*)(bl + 16) = make_uint4(lo[4], lo[5], lo[6], lo[7]);
        atomicAdd(&s_sumsq[nloc], ss);
    };
    auto domma = [&](int buf) {
#pragma unroll
        for (int ks = 0; ks < 2; ks++) {
            const int k0 = ks * 16;
            uint32_t bh[8], bl[8];
#pragma unroll
            for (int nfp = 0; nfp < 2; nfp++) {
                uint32_t addr = sb + OFF_B +
                    (uint32_t)(wn * 32 + nfp * 16 + rB) * APITCH + (k0 + cB) * 2;
                ldm4(&bh[nfp * 4], addr);
                ldm4(&bl[nfp * 4], addr + 10240);
            }
            // per-mf: single a[4] fragment buffer (live set 64+16+4)
#pragma unroll
            for (int mf = 0; mf < 4; mf++) {
                uint32_t a[4];
                uint32_t ah = sb + OFF_A + (uint32_t)buf * 10240 +
                    (uint32_t)(wm * 64 + mf * 16 + rA) * APITCH + (k0 + cA) * 2;
                ldm4(a, ah);
#pragma unroll
                for (int nf = 0; nf < 4; nf++)
                    mma16816(acc[mf][nf], a, bh[nf * 2], bh[nf * 2 + 1]);
#pragma unroll
                for (int nf = 0; nf < 4; nf++)
                    mma16816(acc[mf][nf], a, bl[nf * 2], bl[nf * 2 + 1]);
                ldm4(a, ah + 20480);   // lo variant of A
#pragma unroll
                for (int nf = 0; nf < 4; nf++)
                    mma16816(acc[mf][nf], a, bh[nf * 2], bh[nf * 2 + 1]);
            }
        }
    };

    issueAB(0, 0);
    for (int t = 0; t < NITER; t++) {
        int buf = t & 1;
        asm volatile("cp.async.wait_group 0;" ::: "memory");
        __syncthreads();
        convertB(buf);
        __syncthreads();
        if (t + 1 < NITER) issueAB(t + 1, buf ^ 1);
        domma(buf);
    }
    __syncthreads();
    if (tid < 128)
        s_inv[tid] = (s_sumsq[tid] > 0.0f) ? rsqrtf(s_sumsq[tid]) : 0.0f;
    __syncthreads();

#pragma unroll
    for (int mf = 0; mf < 4; mf++) {
#pragma unroll
        for (int half = 0; half < 2; half++) {
            int rloc = wm * 64 + mf * 16 + (lane >> 2) + half * 8;
            int lab  = s_lab[rloc];
            float ms = s_ms[rloc];
            float* orow = out + (size_t)(row0 + rloc) * CLS_;
#pragma unroll
            for (int nf = 0; nf < 4; nf++) {
                int cloc = wn * 32 + nf * 8 + 2 * (lane & 3);
                int j = col0 + cloc;
                if (j < CLS_) {
                    float v0 = acc[mf][nf][half * 2 + 0] * s_inv[cloc];
                    float v1 = acc[mf][nf][half * 2 + 1] * s_inv[cloc + 1];
                    v0 = fminf(fmaxf(v0, -0.999f), 0.999f);
                    v1 = fminf(fmaxf(v1, -0.999f), 0.999f);
                    float o0, o1;
                    if (j == lab) {
                        float th = acosf(v0) - 0.4f * ms;
                        th = fminf(fmaxf(th, 0.001f), PI_F - 0.001f);
                        o0 = (cosf(th) - (0.4f + 0.4f * ms)) * 64.0f;
                    } else o0 = v0 * 64.0f;
                    if (j + 1 == lab) {
                        float th = acosf(v1) - 0.4f * ms;
                        th = fminf(fmaxf(th, 0.001f), PI_F - 0.001f);
                        o1 = (cosf(th) - (0.4f + 0.4f * ms)) * 64.0f;
                    } else o1 = v1 * 64.0f;
                    *(float2*)(&orow[j]) = make_float2(o0, o1);
                }
            }
        }
    }
}

// ---------------------------------------------------------------------------
// Launch. Inputs: emb f32[512,512], norms f32[512,1], label i32[512],
// csn f32[512], kernel f32[512,70722]
// ---------------------------------------------------------------------------
extern "C" void kernel_launch(void* const* d_in, const int* in_sizes, int n_in,
                              void* d_out, int out_size) {
    const float* emb   = (const float*)d_in[0];
    const float* norms = (const float*)d_in[1];
    const int*   label = (const int*)d_in[2];
    const float* csn   = (const float*)d_in[3];
    const float* kmat  = (const float*)d_in[4];
    float*       out   = (float*)d_out;

    cudaFuncSetAttribute(gemm_hybrid, cudaFuncAttributeMaxDynamicSharedMemorySize,
                         SMEM_TOTAL);

    margin_kernel<<<1, B_>>>(norms, csn);
    prepA_kernel<<<(B_ * EMB_ + 255) / 256, 256>>>(emb);

    gemm_hybrid<<<4 * ((CLS_ + 127) / 128), NT, SMEM_TOTAL>>>(emb, kmat, label, out);
}

// round 14
// speedup vs baseline: 1.5197x; 1.5197x over previous
#include <cuda_runtime.h>
#include <cuda_bf16.h>
#include <math.h>
#include <stdint.h>

#define B_    512
#define EMB_  512
#define CLS_  70722
#define BK    32
#define NITER 16          // 512 / 32
#define NT    256

// dynamic smem offsets (bytes)
#define OFF_A     0        // A tf32 frag-order [buf][k8(4)][mfrag(8)][lane(32)][4] : 2x16384
#define OFF_B     32768    // B tf32 [n(128)][pitch 36] : 18432
#define OFF_STAGE 51200    // fp32 B stage [buf][32][128] : 2x16384
#define OFF_SUMSQ 83968    // 128 f32
#define OFF_INV   84480    // 128 f32
#define OFF_LAB   84992    // 128 i32
#define OFF_MS    85504    // 128 f32
#define SMEM_TOTAL 86016
#define BPITCH 36          // B k-pitch in words; 36 % 32 == 4 -> conflict-free frags

__device__ float g_ms[B_];
// A in tf32, fragment order: [mtile(4)][k8(64)][mfrag(8)][lane(32)][reg(4)]
__device__ __align__(16) float g_Atf[B_ * EMB_];

// ---------------- PTX helpers (sm_80-era, family-target legal) --------------
__device__ __forceinline__ uint32_t smem_u32(const void* p) {
    uint32_t a;
    asm("{ .reg .u64 t; cvta.to.shared.u64 t, %1; cvt.u32.u64 %0, t; }"
        : "=r"(a) : "l"(p));
    return a;
}
__device__ __forceinline__ void cp16(uint32_t dst, const void* src) {
    asm volatile("cp.async.cg.shared.global [%0], [%1], 16;"
                 :: "r"(dst), "l"(src) : "memory");
}
__device__ __forceinline__ void cp8(uint32_t dst, const void* src) {
    asm volatile("cp.async.ca.shared.global [%0], [%1], 8;"
                 :: "r"(dst), "l"(src) : "memory");
}
__device__ __forceinline__ uint32_t f2tf32(float x) {
    uint32_t r;
    asm("cvt.rna.tf32.f32 %0, %1;" : "=r"(r) : "f"(x));
    return r;
}
__device__ __forceinline__ void mma_tf32(float* c, const uint32_t* a,
                                         uint32_t b0, uint32_t b1) {
    asm volatile(
        "mma.sync.aligned.m16n8k8.row.col.f32.tf32.tf32.f32 "
        "{%0,%1,%2,%3}, {%4,%5,%6,%7}, {%8,%9}, {%0,%1,%2,%3};"
        : "+f"(c[0]), "+f"(c[1]), "+f"(c[2]), "+f"(c[3])
        : "r"(a[0]), "r"(a[1]), "r"(a[2]), "r"(a[3]), "r"(b0), "r"(b1));
}

// ---------------------------------------------------------------------------
// Kernel 1: per-row margin scaler ms[i] (single block, 512 threads)
// ---------------------------------------------------------------------------
__global__ void margin_kernel(const float* __restrict__ norms,
                              const float* __restrict__ csn) {
    __shared__ float red[B_];
    int t = threadIdx.x;
    float x = fminf(fmaxf(norms[t], 0.001f), 100.0f);
    x = x / (csn[t] + 0.001f);
    x = fminf(fmaxf(x, 0.001f), 100.0f);

    red[t] = x;
    __syncthreads();
    for (int s = B_ / 2; s > 0; s >>= 1) {
        if (t < s) red[t] += red[t + s];
        __syncthreads();
    }
    float mean = red[0] * (1.0f / B_);
    __syncthreads();
    float d = x - mean;
    red[t] = d * d;
    __syncthreads();
    for (int s = B_ / 2; s > 0; s >>= 1) {
        if (t < s) red[t] += red[t + s];
        __syncthreads();
    }
    float stdv = sqrtf(red[0] / (float)(B_ - 1));
    float msc = (x - mean) / (stdv + 0.001f) * 0.333f;
    g_ms[t] = fminf(fmaxf(msc, -1.0f), 1.0f);
}

// ---------------------------------------------------------------------------
// Kernel 2: permute embeddings fp32 -> tf32 in m16n8k8 A-fragment order.
// g_Atf[mtile][k8][mfrag][lane][reg]:
//   m = mtile*128 + mfrag*16 + (lane>>2) + 8*(reg&1)
//   k = k8*8 + (lane&3) + 4*(reg>>1)
// ---------------------------------------------------------------------------
__global__ void prepA_kernel(const float* __restrict__ E) {
    int i = blockIdx.x * blockDim.x + threadIdx.x;
    if (i >= B_ * EMB_) return;
    int reg   = i & 3;
    int lane  = (i >> 2) & 31;
    int mfrag = (i >> 7) & 7;
    int k8    = (i >> 10) & 63;
    int mtile = i >> 16;
    int m = mtile * 128 + mfrag * 16 + (lane >> 2) + 8 * (reg & 1);
    int k = k8 * 8 + (lane & 3) + 4 * (reg >> 1);
    uint32_t v = f2tf32(E[m * EMB_ + k]);
    ((uint32_t*)g_Atf)[i] = v;
}

// ---------------------------------------------------------------------------
// Kernel 3: single-pass TF32 mma.sync GEMM + fused colnorm + margin epilogue.
// Grid (4 mtiles, 553 ntiles), 256 threads = 8 warps (2M x 4N, 64x32 each).
// ---------------------------------------------------------------------------
__global__ __launch_bounds__(NT, 2) void gemm_tf32(
    const float* __restrict__ Kmat,
    const int* __restrict__ label,
    float* __restrict__ out)
{
    extern __shared__ char smem[];
    const uint32_t sb = smem_u32(smem);
    const int tid  = threadIdx.x;
    const int warp = tid >> 5;
    const int lane = tid & 31;
    const int wm   = warp >> 2;     // 0..1  (64-row slabs)
    const int wn   = warp & 3;      // 0..3  (32-col slabs)
    const int mt   = blockIdx.x;
    const int row0 = mt * 128;
    const int col0 = blockIdx.y * 128;

    float*    s_sumsq = (float*)(smem + OFF_SUMSQ);
    float*    s_inv   = (float*)(smem + OFF_INV);
    int*      s_lab   = (int*)(smem + OFF_LAB);
    float*    s_ms    = (float*)(smem + OFF_MS);
    float*    stage   = (float*)(smem + OFF_STAGE);
    uint32_t* Bt      = (uint32_t*)(smem + OFF_B);

    if (tid < 128) {
        s_sumsq[tid] = 0.0f;
        s_lab[tid]   = label[row0 + tid];
        s_ms[tid]    = g_ms[row0 + tid];
    }

    float acc[4][4][4];
#pragma unroll
    for (int mf = 0; mf < 4; mf++)
#pragma unroll
        for (int nf = 0; nf < 4; nf++)
#pragma unroll
            for (int q = 0; q < 4; q++) acc[mf][nf][q] = 0.0f;

    // ---- async load: A frag-order tf32 (16 KB) + B fp32 stage (16 KB) ----
    auto issueAB = [&](int t, int buf) {
        // A: contiguous 16 KB region for (mt, chunk t) -> 1024 x 16B
        const float* asrc = g_Atf + (size_t)(mt * 64 + t * 4) * 1024;
#pragma unroll
        for (int u = 0; u < 4; u++) {
            int idx = u * 256 + tid;        // 0..1023
            cp16(sb + OFF_A + (uint32_t)buf * 16384 + (uint32_t)idx * 16,
                 asrc + idx * 4);
        }
        // B fp32 stage: 32 k-rows x 128 cols = 2048 x 8B chunks
        // (Kmat rows only 8B-aligned: CLS*4 % 16 == 8)
        int kt = t * BK;
#pragma unroll
        for (int u = 0; u < 8; u++) {
            int idx = u * 256 + tid;        // 0..2047
            int k   = idx >> 6;             // 0..31
            int c2  = idx & 63;             // pair index
            int col = col0 + 2 * c2;
            uint32_t dst = sb + OFF_STAGE + (uint32_t)buf * 16384 +
                           (uint32_t)(k * 128 + 2 * c2) * 4;
            if (col < CLS_) {               // CLS even, col even -> pair valid
                cp8(dst, Kmat + (size_t)(kt + k) * CLS_ + col);
            } else {
                *(float2*)(smem + (dst - sb)) = make_float2(0.0f, 0.0f);
            }
        }
        asm volatile("cp.async.commit_group;" ::: "memory");
    };

    // ---- convert stage fp32 -> B tf32 [n][BPITCH], accumulate sumsq ----
    auto convertB = [&](int buf) {
        const int nloc = tid & 127;
        const int kh   = tid >> 7;          // k half (0/1)
        const float* st = stage + buf * 4096 + kh * 16 * 128 + nloc;
        uint32_t* brow = Bt + nloc * BPITCH + kh * 16;
        float ss = 0.0f;
#pragma unroll
        for (int i = 0; i < 16; i++) {
            float x = st[i * 128];
            ss = fmaf(x, x, ss);
            brow[i] = f2tf32(x);
        }
        atomicAdd(&s_sumsq[nloc], ss);
    };

    // ---- 64 mma per warp per k32 chunk ----
    auto domma = [&](int buf) {
        const int g = lane >> 2;            // groupID
        const int tg = lane & 3;            // threadID in group
#pragma unroll
        for (int k8 = 0; k8 < 4; k8++) {
            // B fragments: n = wn*32 + nf*8 + g ; b0 at k=tg, b1 at k=tg+4
            uint32_t b0[4], b1[4];
#pragma unroll
            for (int nf = 0; nf < 4; nf++) {
                const uint32_t* bp = Bt + (wn * 32 + nf * 8 + g) * BPITCH + k8 * 8 + tg;
                b0[nf] = bp[0];
                b1[nf] = bp[4];
            }
#pragma unroll
            for (int mf = 0; mf < 4; mf++) {
                uint32_t a[4];
                *(uint4*)a = *(const uint4*)(smem + OFF_A + buf * 16384 +
                    ((k8 * 8 + wm * 4 + mf) * 32 + lane) * 16);
#pragma unroll
                for (int nf = 0; nf < 4; nf++)
                    mma_tf32(acc[mf][nf], a, b0[nf], b1[nf]);
            }
        }
    };

    issueAB(0, 0);
    for (int t = 0; t < NITER; t++) {
        int buf = t & 1;
        asm volatile("cp.async.wait_group 0;" ::: "memory");
        __syncthreads();                 // A/stage(t) landed; domma(t-1) readers done
        convertB(buf);
        __syncthreads();                 // Bt visible to all warps
        if (t + 1 < NITER) issueAB(t + 1, buf ^ 1);
        domma(buf);
    }
    __syncthreads();
    if (tid < 128)
        s_inv[tid] = (s_sumsq[tid] > 0.0f) ? rsqrtf(s_sumsq[tid]) : 0.0f;
    __syncthreads();

    // --- epilogue: fragments -> normalize/clip/margin -> float2 stores ---
    const float PI_F = 3.14159265358979323846f;
#pragma unroll
    for (int mf = 0; mf < 4; mf++) {
#pragma unroll
        for (int half = 0; half < 2; half++) {
            int rloc = wm * 64 + mf * 16 + (lane >> 2) + half * 8;
            int lab  = s_lab[rloc];
            float ms = s_ms[rloc];
            float* orow = out + (size_t)(row0 + rloc) * CLS_;
#pragma unroll
            for (int nf = 0; nf < 4; nf++) {
                int cloc = wn * 32 + nf * 8 + 2 * (lane & 3);
                int j = col0 + cloc;
                if (j < CLS_) {          // CLS even, j even -> pair valid
                    float v0 = acc[mf][nf][half * 2 + 0] * s_inv[cloc];
                    float v1 = acc[mf][nf][half * 2 + 1] * s_inv[cloc + 1];
                    v0 = fminf(fmaxf(v0, -0.999f), 0.999f);
                    v1 = fminf(fmaxf(v1, -0.999f), 0.999f);
                    float o0, o1;
                    if (j == lab) {
                        float th = acosf(v0) - 0.4f * ms;
                        th = fminf(fmaxf(th, 0.001f), PI_F - 0.001f);
                        o0 = (cosf(th) - (0.4f + 0.4f * ms)) * 64.0f;
                    } else o0 = v0 * 64.0f;
                    if (j + 1 == lab) {
                        float th = acosf(v1) - 0.4f * ms;
                        th = fminf(fmaxf(th, 0.001f), PI_F - 0.001f);
                        o1 = (cosf(th) - (0.4f + 0.4f * ms)) * 64.0f;
                    } else o1 = v1 * 64.0f;
                    *(float2*)(&orow[j]) = make_float2(o0, o1);
                }
            }
        }
    }
}

// ---------------------------------------------------------------------------
// Launch. Inputs: emb f32[512,512], norms f32[512,1], label i32[512],
// csn f32[512], kernel f32[512,70722]
// ---------------------------------------------------------------------------
extern "C" void kernel_launch(void* const* d_in, const int* in_sizes, int n_in,
                              void* d_out, int out_size) {
    const float* emb   = (const float*)d_in[0];
    const float* norms = (const float*)d_in[1];
    const int*   label = (const int*)d_in[2];
    const float* csn   = (const float*)d_in[3];
    const float* kmat  = (const float*)d_in[4];
    float*       out   = (float*)d_out;

    cudaFuncSetAttribute(gemm_tf32, cudaFuncAttributeMaxDynamicSharedMemorySize,
                         SMEM_TOTAL);

    margin_kernel<<<1, B_>>>(norms, csn);
    prepA_kernel<<<(B_ * EMB_ + 255) / 256, 256>>>(emb);

    dim3 grid(4, (CLS_ + 127) / 128);   // mtile fastest -> B tiles L2-shared
    gemm_tf32<<<grid, NT, SMEM_TOTAL>>>(kmat, label, out);
}